// round 14
// baseline (speedup 1.0000x reference)
#include <cuda_runtime.h>
#include <cstdint>

// ---------------------------------------------------------------------------
// ClockworkGRU  v14 (= v13 + shallow-task rebalance):
//   * streamed r/z/hn dots split into 64-deep segments (b3 r: 128-deep for
//     SMEM budget) -> latency-wave critical path ~halved on even steps.
//   * block 0 redundant per rank, 2x64-deep 2-col tasks (256 = CTA threads).
//   * odd steps: no cluster barriers; even steps: split trailing barrier.
// ---------------------------------------------------------------------------

#define GM 32768
#define GK 512
#define GN 512
#define SEQ_LEN 512
#define NBATCH 64

__device__ float g_proj[3ull * GM * GN];

__constant__ int c_OFF[4]  = {0, 128, 384, 768};
__constant__ int c_SRs[4]  = {0, 4, 6, 4};       // r segs (b1/b2: 64d, b3: 128d)
__constant__ int c_RB[4]   = {0, 0, 512, 1664};  // r partial bases in rp
__constant__ int c_SZs[4]  = {0, 4, 6, 8};       // z segs (64-deep)
__constant__ int c_ZB[4]   = {0, 0, 256, 640};   // z partial bases in zp
__constant__ int c_SHs[4]  = {0, 4, 6, 8};       // hn segs (64-deep)
__constant__ int c_HB[4]   = {0, 512, 768, 1152};// hn bases (alias rp)

// ---------------- helpers ----------------------------------------------------
__device__ __forceinline__ unsigned long long pack2(float x, float y) {
    unsigned long long r;
    asm("mov.b64 %0, {%1, %2};" : "=l"(r) : "f"(x), "f"(y));
    return r;
}
__device__ __forceinline__ void fma2(unsigned long long& d,
                                     unsigned long long a,
                                     unsigned long long b) {
    asm("fma.rn.f32x2 %0, %1, %2, %0;" : "+l"(d) : "l"(a), "l"(b));
}
__device__ __forceinline__ float2 unpack2(unsigned long long v) {
    float2 r;
    asm("mov.b64 {%0, %1}, %2;" : "=f"(r.x), "=f"(r.y) : "l"(v));
    return r;
}
__device__ __forceinline__ float sigmoidf_(float x) {
    return 1.0f / (1.0f + __expf(-x));
}
__device__ __forceinline__ uint32_t smem_u32(const void* p) {
    return (uint32_t)__cvta_generic_to_shared(p);
}
__device__ __forceinline__ uint32_t mapa_u32(uint32_t addr, uint32_t rank) {
    uint32_t r;
    asm("mapa.shared::cluster.u32 %0, %1, %2;" : "=r"(r) : "r"(addr), "r"(rank));
    return r;
}
__device__ __forceinline__ void st_cluster_b64(uint32_t a, float x, float y) {
    unsigned long long v = pack2(x, y);
    asm volatile("st.shared::cluster.b64 [%0], %1;" :: "r"(a), "l"(v) : "memory");
}
#define CLUSTER_SYNC() do {                                           \
    asm volatile("barrier.cluster.arrive.aligned;" ::: "memory");     \
    asm volatile("barrier.cluster.wait.aligned;"   ::: "memory");     \
} while (0)
#define CLUSTER_ARRIVE() \
    asm volatile("barrier.cluster.arrive.aligned;" ::: "memory")
#define CLUSTER_WAIT() \
    asm volatile("barrier.cluster.wait.aligned;"   ::: "memory")

// ---------------------------------------------------------------------------
// Clockwork-sparse GEMM (unchanged — measured ~0.43 ms)
// ---------------------------------------------------------------------------
#define BM 128
#define BN 128
#define BKK 8

__global__ void __launch_bounds__(256) gemm3_kernel(
    const float* __restrict__ A,
    const float* __restrict__ W0, const float* __restrict__ b0,
    const float* __restrict__ W1, const float* __restrict__ b1,
    const float* __restrict__ W2, const float* __restrict__ b2)
{
    __shared__ float As[BKK][BM];
    __shared__ float Bs[BKK][BN];

    const int zi = blockIdx.z;
    const int z  = zi >> 2;
    const int cb = zi & 3;
    const int rpb_log = 9 - cb;
    const int ntiles = (NBATCH << rpb_log) >> 7;
    if ((int)blockIdx.y >= ntiles) return;

    const float* W    = (z == 0) ? W0 : (z == 1 ? W1 : W2);
    const float* bias = (z == 0) ? b0 : (z == 1 ? b1 : b2);
    float* C = g_proj + (size_t)z * GM * GN;

    const int m0 = blockIdx.y * BM;
    const int n0 = cb * 128;
    const int tid = threadIdx.x;

    const int a_row = tid >> 1;
    const int a_k   = (tid & 1) * 4;
    const int b_row = tid >> 5;
    const int b_col = (tid & 31) * 4;

    const int warp = tid >> 5;
    const int lane = tid & 31;
    const int row0 = (warp & 3) * 32 + (lane & 3) * 8;
    const int col0 = (warp >> 2) * 64 + (lane >> 2) * 8;

    const int rpb_mask = (1 << rpb_log) - 1;
    const int gA = m0 + a_row;
    const int arow_act = ((gA >> rpb_log) << 9) + ((gA & rpb_mask) << cb);

    unsigned long long acc[8][4];
#pragma unroll
    for (int i = 0; i < 8; i++)
#pragma unroll
        for (int j = 0; j < 4; j++) acc[i][j] = 0ull;

    const float* Aptr = A + (size_t)arow_act * GK + a_k;
    const float* Wptr = W + (size_t)b_row * GN + n0 + b_col;

    float4 ra = *(const float4*)Aptr;
    float4 rb = *(const float4*)Wptr;

    const int KT = GK / BKK;
    for (int kt = 0; kt < KT; kt++) {
        As[a_k + 0][a_row] = ra.x;
        As[a_k + 1][a_row] = ra.y;
        As[a_k + 2][a_row] = ra.z;
        As[a_k + 3][a_row] = ra.w;
        *(float4*)&Bs[b_row][b_col] = rb;
        __syncthreads();

        if (kt + 1 < KT) {
            ra = *(const float4*)(Aptr + (kt + 1) * BKK);
            rb = *(const float4*)(Wptr + (size_t)(kt + 1) * BKK * GN);
        }

#pragma unroll
        for (int k = 0; k < BKK; k++) {
            float4 a0 = *(const float4*)&As[k][row0];
            float4 a1 = *(const float4*)&As[k][row0 + 4];
            ulonglong2 bq0 = *(const ulonglong2*)&Bs[k][col0];
            ulonglong2 bq1 = *(const ulonglong2*)&Bs[k][col0 + 4];
            unsigned long long av[8];
            av[0] = pack2(a0.x, a0.x); av[1] = pack2(a0.y, a0.y);
            av[2] = pack2(a0.z, a0.z); av[3] = pack2(a0.w, a0.w);
            av[4] = pack2(a1.x, a1.x); av[5] = pack2(a1.y, a1.y);
            av[6] = pack2(a1.z, a1.z); av[7] = pack2(a1.w, a1.w);
#pragma unroll
            for (int i = 0; i < 8; i++) {
                fma2(acc[i][0], av[i], bq0.x);
                fma2(acc[i][1], av[i], bq0.y);
                fma2(acc[i][2], av[i], bq1.x);
                fma2(acc[i][3], av[i], bq1.y);
            }
        }
        __syncthreads();
    }

    float bb[8];
#pragma unroll
    for (int j = 0; j < 8; j++) bb[j] = bias[n0 + col0 + j];

#pragma unroll
    for (int i = 0; i < 8; i++) {
        float o[8];
#pragma unroll
        for (int jp = 0; jp < 4; jp++) {
            float2 v = unpack2(acc[i][jp]);
            o[2 * jp]     = v.x + bb[2 * jp];
            o[2 * jp + 1] = v.y + bb[2 * jp + 1];
        }
        const int g2 = m0 + row0 + i;
        const int crow = ((g2 >> rpb_log) << 9) + ((g2 & rpb_mask) << cb);
        size_t base = (size_t)crow * GN + n0 + col0;
        *(float4*)&C[base]     = make_float4(o[0], o[1], o[2], o[3]);
        *(float4*)&C[base + 4] = make_float4(o[4], o[5], o[6], o[7]);
    }
}

// ---------------------------------------------------------------------------
// warp-coalesced 2-row dots
// ---------------------------------------------------------------------------

// lanes < WIDE each own 4 consecutive cols per k-row; KD rows, 8+8 dbl-buffer.
template<int WIDE, int KD>
__device__ __forceinline__ void wdot_wide2(const float* __restrict__ Wp, int stride,
                                           const float* __restrict__ h0,
                                           const float* __restrict__ h1,
                                           float* a0, float* a1, int lane)
{
    const float* p = Wp + lane * 4;
    float4 A[8], B[8];
#pragma unroll
    for (int r = 0; r < 8; r++) A[r] = *(const float4*)(p + (size_t)r * stride);
#pragma unroll
    for (int kb = 0; kb < KD; kb += 16) {
#pragma unroll
        for (int r = 0; r < 8; r++)
            B[r] = *(const float4*)(p + (size_t)(kb + 8 + r) * stride);
#pragma unroll
        for (int r = 0; r < 8; r++) {
            float x0 = h0[kb + r], x1 = h1[kb + r];
            a0[0] = fmaf(x0, A[r].x, a0[0]); a0[1] = fmaf(x0, A[r].y, a0[1]);
            a0[2] = fmaf(x0, A[r].z, a0[2]); a0[3] = fmaf(x0, A[r].w, a0[3]);
            a1[0] = fmaf(x1, A[r].x, a1[0]); a1[1] = fmaf(x1, A[r].y, a1[1]);
            a1[2] = fmaf(x1, A[r].z, a1[2]); a1[3] = fmaf(x1, A[r].w, a1[3]);
        }
        if (kb + 16 < KD) {
#pragma unroll
            for (int r = 0; r < 8; r++)
                A[r] = *(const float4*)(p + (size_t)(kb + 16 + r) * stride);
        }
#pragma unroll
        for (int r = 0; r < 8; r++) {
            float x0 = h0[kb + 8 + r], x1 = h1[kb + 8 + r];
            a0[0] = fmaf(x0, B[r].x, a0[0]); a0[1] = fmaf(x0, B[r].y, a0[1]);
            a0[2] = fmaf(x0, B[r].z, a0[2]); a0[3] = fmaf(x0, B[r].w, a0[3]);
            a1[0] = fmaf(x1, B[r].x, a1[0]); a1[1] = fmaf(x1, B[r].y, a1[1]);
            a1[2] = fmaf(x1, B[r].z, a1[2]); a1[3] = fmaf(x1, B[r].w, a1[3]);
        }
    }
}

// 32-col window dot over 64 rows; all 16 loads prefetched; shfl reduce;
// lanes 0-7 hold column sums.
__device__ __forceinline__ void wdot_w8(const float* __restrict__ Wp, int stride,
                                        const float* __restrict__ h0,
                                        const float* __restrict__ h1,
                                        float* a0, float* a1, int lane)
{
    const int sr = lane >> 3, sc = lane & 7;
    const float* p = Wp + sr * stride + sc * 4;
    float4 A[8], B[8];
#pragma unroll
    for (int i = 0; i < 8; i++)
        A[i] = *(const float4*)(p + (size_t)(i * 4) * stride);
#pragma unroll
    for (int i = 0; i < 8; i++)
        B[i] = *(const float4*)(p + (size_t)((i + 8) * 4) * stride);
#pragma unroll
    for (int i = 0; i < 8; i++) {
        float x0 = h0[i * 4 + sr], x1 = h1[i * 4 + sr];
        a0[0] = fmaf(x0, A[i].x, a0[0]); a0[1] = fmaf(x0, A[i].y, a0[1]);
        a0[2] = fmaf(x0, A[i].z, a0[2]); a0[3] = fmaf(x0, A[i].w, a0[3]);
        a1[0] = fmaf(x1, A[i].x, a1[0]); a1[1] = fmaf(x1, A[i].y, a1[1]);
        a1[2] = fmaf(x1, A[i].z, a1[2]); a1[3] = fmaf(x1, A[i].w, a1[3]);
    }
#pragma unroll
    for (int i = 0; i < 8; i++) {
        float x0 = h0[(i + 8) * 4 + sr], x1 = h1[(i + 8) * 4 + sr];
        a0[0] = fmaf(x0, B[i].x, a0[0]); a0[1] = fmaf(x0, B[i].y, a0[1]);
        a0[2] = fmaf(x0, B[i].z, a0[2]); a0[3] = fmaf(x0, B[i].w, a0[3]);
        a1[0] = fmaf(x1, B[i].x, a1[0]); a1[1] = fmaf(x1, B[i].y, a1[1]);
        a1[2] = fmaf(x1, B[i].z, a1[2]); a1[3] = fmaf(x1, B[i].w, a1[3]);
    }
#pragma unroll
    for (int j = 0; j < 4; j++) {
        a0[j] += __shfl_xor_sync(0xffffffffu, a0[j], 8);
        a0[j] += __shfl_xor_sync(0xffffffffu, a0[j], 16);
        a1[j] += __shfl_xor_sync(0xffffffffu, a1[j], 8);
        a1[j] += __shfl_xor_sync(0xffffffffu, a1[j], 16);
    }
}

// block0 SMEM dot: 64-deep, 2 cols, 2 rows (full matrix stride 128 floats)
__device__ __forceinline__ void dot_b0_64(const float* __restrict__ w,
                                          const float* __restrict__ h0,
                                          const float* __restrict__ h1,
                                          float2& a0, float2& a1)
{
#pragma unroll 16
    for (int k = 0; k < 64; k++) {
        float2 ww = *(const float2*)&w[k << 7];
        float x0 = h0[k], x1 = h1[k];
        a0.x = fmaf(x0, ww.x, a0.x); a0.y = fmaf(x0, ww.y, a0.y);
        a1.x = fmaf(x1, ww.x, a1.x); a1.y = fmaf(x1, ww.y, a1.y);
    }
}

__device__ __forceinline__ void fold4(float* a, const float4& b) {
    a[0] += b.x; a[1] += b.y; a[2] += b.z; a[3] += b.w;
}

// ---------------------------------------------------------------------------
__global__ void __launch_bounds__(512, 1) __cluster_dims__(4, 1, 1)
scan_kernel(
    const float* __restrict__ ch0, const float* __restrict__ cr0, const float* __restrict__ cz0,
    const float* __restrict__ ch1, const float* __restrict__ cr1, const float* __restrict__ cz1,
    const float* __restrict__ ch2, const float* __restrict__ cr2, const float* __restrict__ cz2,
    const float* __restrict__ ch3, const float* __restrict__ cr3, const float* __restrict__ cz3,
    float* __restrict__ out)
{
    extern __shared__ float smem[];
    float* h_s   = smem;              // 2 x 512
    float* rh_s  = smem + 1024;       // 2 x 1280
    float* b0rp  = smem + 3584;       // 512: [2 seg][2 row][128]
    float* b0zp  = smem + 4096;       // 512
    float* rp    = smem + 4608;       // 2688 streamed r partials (+ hn alias)
    float* zp    = smem + 7296;       // 1152 streamed z partials
    float* cr0_s = smem + 8448;       // 128 x 128 FULL
    float* cz0_s = smem + 24832;      // 128 x 128 FULL
    float* ch0_s = smem + 41216;      // 128 x 128 FULL (end 57600 = 230,400 B)

    const int rank = blockIdx.x & 3;
    const int bp   = blockIdx.x >> 2;
    const int tid  = threadIdx.x;
    const int wid  = tid >> 5;
    const int lane = tid & 31;

    // preload FULL block-0 matrices
    {
        const float4* s1 = (const float4*)cr0; float4* d1 = (float4*)cr0_s;
        const float4* s2 = (const float4*)cz0; float4* d2 = (float4*)cz0_s;
        const float4* s3 = (const float4*)ch0; float4* d3 = (float4*)ch0_s;
        for (int i = tid; i < 4096; i += 512) {
            d1[i] = s1[i]; d2[i] = s2[i]; d3[i] = s3[i];
        }
    }
    h_s[tid] = 0.0f; h_s[512 + tid] = 0.0f;
    __syncthreads();
    CLUSTER_SYNC();

    uint32_t peer_rh[3], peer_h[3];
    {
        int p = 0;
        for (int r = 0; r < 4; r++) {
            if (r == rank) continue;
            peer_rh[p] = mapa_u32(smem_u32(rh_s), (uint32_t)r);
            peer_h[p]  = mapa_u32(smem_u32(h_s),  (uint32_t)r);
            p++;
        }
    }

    const float* xt  = g_proj;
    const float* xrt = g_proj + (size_t)GM * GN;
    const float* xzt = g_proj + 2ull * GM * GN;

    for (int t = 0; t < SEQ_LEN; t++) {
        const bool aa1 = (t & 1) == 0, aa2 = (t & 3) == 0, aa3 = (t & 7) == 0;
        int sact[3]; int ns = 0;
        if (aa1) sact[ns++] = 1;
        if (aa2) sact[ns++] = 2;
        if (aa3) sact[ns++] = 3;

        const size_t xr0 = ((size_t)(bp * 2 + 0) * SEQ_LEN + t) * GN;
        const size_t xr1 = ((size_t)(bp * 2 + 1) * SEQ_LEN + t) * GN;

        // complete the split barrier from the previous even step
        if (aa1 && t > 0) CLUSTER_WAIT();

        // ============ pass 1: r/z dots → partial slots ======================
        // (a) warp tasks: streamed blocks (64-deep segs; b3 r 128-deep)
        if (ns > 0) {
            const int nwt = (aa1 ? 12 : 0) + (aa2 ? 12 : 0) + (aa3 ? 12 : 0);
            for (int wt = wid; wt < nwt; wt += 16) {
                int k = wt;
                float A0[4] = {0,0,0,0}, A1[4] = {0,0,0,0};
                if (aa1) {
                    if (k < 8) {                      // b1 r: 2 grp x 4 seg64
                        const int seg = k >> 1, g = k & 1;
                        wdot_w8(cr1 + (size_t)(seg * 64) * 256
                                    + rank * 64 + g * 32, 256,
                                h_s + seg * 64, h_s + 512 + seg * 64,
                                A0, A1, lane);
                        if (lane < 8) {
                            const int c = g * 32 + lane * 4;
                            if (seg == 0) {
                                fold4(A0, *(const float4*)&xrt[xr0 + rank * 64 + c]);
                                fold4(A1, *(const float4*)&xrt[xr1 + rank * 64 + c]);
                            }
                            float* P = rp + seg * 128 + c;
                            *(float4*)P        = make_float4(A0[0],A0[1],A0[2],A0[3]);
                            *(float4*)(P + 64) = make_float4(A1[0],A1[1],A1[2],A1[3]);
                        }
                        continue;
                    }
                    k -= 8;
                    if (k < 4) {                      // b1 z: 4 seg64
                        const int seg = k;
                        wdot_w8(cz1 + (size_t)(seg * 64) * 128 + rank * 32, 128,
                                h_s + seg * 64, h_s + 512 + seg * 64,
                                A0, A1, lane);
                        if (lane < 8) {
                            const int c = lane * 4;
                            if (seg == 0) {
                                fold4(A0, *(const float4*)&xzt[xr0 + 128 + rank * 32 + c]);
                                fold4(A1, *(const float4*)&xzt[xr1 + 128 + rank * 32 + c]);
                            }
                            float* P = zp + seg * 64 + c;
                            *(float4*)P        = make_float4(A0[0],A0[1],A0[2],A0[3]);
                            *(float4*)(P + 32) = make_float4(A1[0],A1[1],A1[2],A1[3]);
                        }
                        continue;
                    }
                    k -= 4;
                }
                if (aa2) {
                    if (k < 6) {                      // b2 r: 6 seg64
                        const int seg = k;
                        if (lane < 24) {
                            wdot_wide2<24, 64>(cr2 + (size_t)(seg * 64) * 384
                                                   + rank * 96, 384,
                                               h_s + seg * 64,
                                               h_s + 512 + seg * 64,
                                               A0, A1, lane);
                            const int c = lane * 4;
                            if (seg == 0) {
                                fold4(A0, *(const float4*)&xrt[xr0 + rank * 96 + c]);
                                fold4(A1, *(const float4*)&xrt[xr1 + rank * 96 + c]);
                            }
                            float* P = rp + 512 + seg * 192 + c;
                            *(float4*)P        = make_float4(A0[0],A0[1],A0[2],A0[3]);
                            *(float4*)(P + 96) = make_float4(A1[0],A1[1],A1[2],A1[3]);
                        }
                        continue;
                    }
                    k -= 6;
                    if (k < 6) {                      // b2 z: 6 seg64
                        const int seg = k;
                        wdot_w8(cz2 + (size_t)(seg * 64) * 128 + rank * 32, 128,
                                h_s + seg * 64, h_s + 512 + seg * 64,
                                A0, A1, lane);
                        if (lane < 8) {
                            const int c = lane * 4;
                            if (seg == 0) {
                                fold4(A0, *(const float4*)&xzt[xr0 + 256 + rank * 32 + c]);
                                fold4(A1, *(const float4*)&xzt[xr1 + 256 + rank * 32 + c]);
                            }
                            float* P = zp + 256 + seg * 64 + c;
                            *(float4*)P        = make_float4(A0[0],A0[1],A0[2],A0[3]);
                            *(float4*)(P + 32) = make_float4(A1[0],A1[1],A1[2],A1[3]);
                        }
                        continue;
                    }
                    k -= 6;
                }
                if (k < 4) {                          // b3 r: 4 seg128
                    const int seg = k;
                    wdot_wide2<32, 128>(cr3 + (size_t)(seg * 128) * 512
                                            + rank * 128, 512,
                                        h_s + seg * 128, h_s + 512 + seg * 128,
                                        A0, A1, lane);
                    const int c = lane * 4;
                    if (seg == 0) {
                        fold4(A0, *(const float4*)&xrt[xr0 + rank * 128 + c]);
                        fold4(A1, *(const float4*)&xrt[xr1 + rank * 128 + c]);
                    }
                    float* P = rp + 1664 + seg * 256 + c;
                    *(float4*)P         = make_float4(A0[0],A0[1],A0[2],A0[3]);
                    *(float4*)(P + 128) = make_float4(A1[0],A1[1],A1[2],A1[3]);
                } else {                              // b3 z: 8 seg64
                    const int seg = k - 4;
                    wdot_w8(cz3 + (size_t)(seg * 64) * 128 + rank * 32, 128,
                            h_s + seg * 64, h_s + 512 + seg * 64, A0, A1, lane);
                    if (lane < 8) {
                        const int c = lane * 4;
                        if (seg == 0) {
                            fold4(A0, *(const float4*)&xzt[xr0 + 384 + rank * 32 + c]);
                            fold4(A1, *(const float4*)&xzt[xr1 + 384 + rank * 32 + c]);
                        }
                        float* P = zp + 640 + seg * 64 + c;
                        *(float4*)P        = make_float4(A0[0],A0[1],A0[2],A0[3]);
                        *(float4*)(P + 32) = make_float4(A1[0],A1[1],A1[2],A1[3]);
                    }
                }
            }
        }
        // (b) block0 r/z tasks (redundant, SMEM): 256 tasks on tid>=256
        //     task = (gate, seg<2, colpair<64), 64-deep, 2 cols, 2 rows
        if (tid >= 256) {
            const int tk = tid - 256;
            const bool isZ = tk >= 128;
            const int r2 = tk & 127;
            const int seg = r2 >> 6, c = (r2 & 63) * 2;
            float2 A0 = {0.f, 0.f}, A1 = {0.f, 0.f};
            const float* w = (isZ ? cz0_s : cr0_s) + (seg * 64) * 128 + c;
            dot_b0_64(w, h_s + seg * 64, h_s + 512 + seg * 64, A0, A1);
            if (seg == 0) {
                const float* xb = isZ ? xzt : xrt;
                float2 B0 = *(const float2*)&xb[xr0 + c];
                float2 B1 = *(const float2*)&xb[xr1 + c];
                A0.x += B0.x; A0.y += B0.y;
                A1.x += B1.x; A1.y += B1.y;
            }
            float* P = (isZ ? b0zp : b0rp) + seg * 256 + c;
            *(float2*)P         = A0;
            *(float2*)(P + 128) = A1;
        }
        __syncthreads();

        // ============ pass 2: reduce r → rh =================================
        {
            int pcount[3]; int nst = 0;
            for (int a = 0; a < ns; a++) {
                pcount[a] = (sact[a] + 1) * 16;
                nst += pcount[a];
            }
            const int total2 = 128 + 2 * nst;
            for (int s = tid; s < total2; s += 512) {
                if (s < 128) {                  // block0 (local only)
                    const int row = s & 1;
                    const int c = (s >> 1) * 2;
                    const float* P = b0rp + row * 128 + c;
                    const float s0 = P[0] + P[256];
                    const float s1 = P[1] + P[257];
                    const float* hh = h_s + row * 512;
                    rh_s[row * 1280 + c]     = sigmoidf_(s0) * hh[c];
                    rh_s[row * 1280 + c + 1] = sigmoidf_(s1) * hh[c + 1];
                } else {                        // streamed blocks + exchange
                    const int s2 = s - 128;
                    const int row = s2 & 1;
                    int p = s2 >> 1;
                    int i = 1;
                    for (int a = 0; a < ns; a++) {
                        if (p < pcount[a]) { i = sact[a]; break; }
                        p -= pcount[a];
                    }
                    const int colsP = (i + 1) * 32;
                    const int c2 = p * 2;
                    const int j = rank * colsP + c2;
                    const float* P = rp + c_RB[i] + row * colsP + c2;
                    float s0 = 0.f, s1 = 0.f;
                    const int nsg = c_SRs[i];
                    for (int sg = 0; sg < nsg; sg++) {
                        s0 += P[sg * 2 * colsP];
                        s1 += P[sg * 2 * colsP + 1];
                    }
                    const float* hh = h_s + row * 512;
                    const float v0 = sigmoidf_(s0) * hh[j];
                    const float v1 = sigmoidf_(s1) * hh[j + 1];
                    const int idx = c_OFF[i] + j;
                    rh_s[row * 1280 + idx]     = v0;
                    rh_s[row * 1280 + idx + 1] = v1;
                    const uint32_t off = (uint32_t)(row * 1280 + idx) * 4u;
                    st_cluster_b64(peer_rh[0] + off, v0, v1);
                    st_cluster_b64(peer_rh[1] + off, v0, v1);
                    st_cluster_b64(peer_rh[2] + off, v0, v1);
                }
            }
        }
        if (ns > 0) CLUSTER_SYNC();
        else        __syncthreads();

        // ============ pass 3: hn dots =======================================
        // (a) warp tasks: streamed blocks, 64-deep segs
        if (ns > 0) {
            const int nwh = (aa1 ? 4 : 0) + (aa2 ? 6 : 0) + (aa3 ? 8 : 0);
            for (int wt = wid; wt < nwh; wt += 16) {
                int k = wt;
                float A0[4] = {0,0,0,0}, A1[4] = {0,0,0,0};
                int i, seg;
                const float* base;
                if (aa1 && k < 4)      { i = 1; seg = k; base = ch1; }
                else {
                    if (aa1) k -= 4;
                    if (aa2 && k < 6)  { i = 2; seg = k; base = ch2; }
                    else { if (aa2) k -= 6; i = 3; seg = k; base = ch3; }
                }
                wdot_w8(base + (size_t)(seg * 64) * 128 + rank * 32, 128,
                        rh_s + c_OFF[i] + seg * 64,
                        rh_s + 1280 + c_OFF[i] + seg * 64, A0, A1, lane);
                if (lane < 8) {
                    const int c = lane * 4;
                    if (seg == 0) {
                        const int gc = (i << 7) + rank * 32 + c;
                        fold4(A0, *(const float4*)&xt[xr0 + gc]);
                        fold4(A1, *(const float4*)&xt[xr1 + gc]);
                    }
                    float* P = rp + c_HB[i] + seg * 64 + c;
                    *(float4*)P        = make_float4(A0[0],A0[1],A0[2],A0[3]);
                    *(float4*)(P + 32) = make_float4(A1[0],A1[1],A1[2],A1[3]);
                }
            }
        }
        // (b) block0 hn tasks (redundant, SMEM): 128 tasks on tid>=384
        if (tid >= 384) {
            const int tk = tid - 384;
            const int seg = tk >> 6, c = (tk & 63) * 2;
            float2 A0 = {0.f, 0.f}, A1 = {0.f, 0.f};
            dot_b0_64(ch0_s + (seg * 64) * 128 + c,
                      rh_s + seg * 64, rh_s + 1280 + seg * 64, A0, A1);
            if (seg == 0) {
                float2 B0 = *(const float2*)&xt[xr0 + c];
                float2 B1 = *(const float2*)&xt[xr1 + c];
                A0.x += B0.x; A0.y += B0.y;
                A1.x += B1.x; A1.y += B1.y;
            }
            float* P = rp + seg * 256 + c;   // b0h aliases rp[0:512)
            *(float2*)P         = A0;
            *(float2*)(P + 128) = A1;
        }
        __syncthreads();

        // ============ pass 4: reduce z/hn, gate, update h ===================
        {
            const int total4 = 128 + 2 * (ns * 16);
            for (int s = tid; s < total4; s += 512) {
                if (s < 128) {                  // block0 (local only)
                    const int row = s & 1;
                    const int c = (s >> 1) * 2;
                    const float* Pz = b0zp + row * 128 + c;
                    const float* Ph = rp + row * 128 + c;
                    const float z0 = Pz[0] + Pz[256];
                    const float z1 = Pz[1] + Pz[257];
                    const float n0 = Ph[0] + Ph[256];
                    const float n1 = Ph[1] + Ph[257];
                    const float zz0 = sigmoidf_(z0), zz1 = sigmoidf_(z1);
                    const float hn0 = sigmoidf_(n0), hn1 = sigmoidf_(n1);
                    float* hh = h_s + row * 512;
                    hh[c]     = zz0 * hn0 + (1.0f - zz0) * hh[c];
                    hh[c + 1] = zz1 * hn1 + (1.0f - zz1) * hh[c + 1];
                } else {                        // streamed + exchange
                    const int s2 = s - 128;
                    const int row = s2 & 1;
                    const int p = s2 >> 1;
                    const int i = sact[p >> 4];
                    const int c2 = (p & 15) * 2;
                    const int lc = rank * 32 + c2;
                    const int gc = (i << 7) + lc;
                    const float* Pz = zp + c_ZB[i] + row * 32 + c2;
                    const float* Ph = rp + c_HB[i] + row * 32 + c2;
                    float z0 = 0.f, z1 = 0.f, n0 = 0.f, n1 = 0.f;
                    const int nz = c_SZs[i];
                    for (int sg = 0; sg < nz; sg++) {
                        z0 += Pz[sg * 64]; z1 += Pz[sg * 64 + 1];
                    }
                    const int nh = c_SHs[i];
                    for (int sg = 0; sg < nh; sg++) {
                        n0 += Ph[sg * 64]; n1 += Ph[sg * 64 + 1];
                    }
                    const float zz0 = sigmoidf_(z0), zz1 = sigmoidf_(z1);
                    const float hn0 = sigmoidf_(n0), hn1 = sigmoidf_(n1);
                    float* hh = h_s + row * 512;
                    const float v0 = zz0 * hn0 + (1.0f - zz0) * hh[gc];
                    const float v1 = zz1 * hn1 + (1.0f - zz1) * hh[gc + 1];
                    hh[gc] = v0; hh[gc + 1] = v1;
                    const uint32_t off = (uint32_t)(row * 512 + gc) * 4u;
                    st_cluster_b64(peer_h[0] + off, v0, v1);
                    st_cluster_b64(peer_h[1] + off, v0, v1);
                    st_cluster_b64(peer_h[2] + off, v0, v1);
                }
            }
        }
        __syncthreads();

        // ============ output =================================================
        if (ns > 0) {
            if (tid < 256) {
                const int row = tid >> 7;
                const int idx = tid & 127;
                const int i = idx >> 5, c = idx & 31;
                const int gc = i * 128 + rank * 32 + c;
                const size_t xr = row ? xr1 : xr0;
                out[xr + gc] = h_s[row * 512 + gc];
            } else if (tid < 448) {
                // pre-write row t+1 for blocks 1-3 (unchanged at odd t+1)
                const int s = tid - 256;
                const int row = s / 96;
                const int idx = s % 96;
                const int i = 1 + (idx >> 5), c = idx & 31;
                const int gc = i * 128 + rank * 32 + c;
                const size_t xr = (row ? xr1 : xr0) + GN;
                out[xr + gc] = h_s[row * 512 + gc];
            }
            CLUSTER_ARRIVE();
        } else {
            if (tid < 64) {
                const int row = tid >> 5, c = tid & 31;
                const int gc = rank * 32 + c;
                const size_t xr = row ? xr1 : xr0;
                out[xr + gc] = h_s[row * 512 + gc];
            }
        }
    }
}

// ---------------------------------------------------------------------------
extern "C" void kernel_launch(void* const* d_in, const int* in_sizes, int n_in,
                              void* d_out, int out_size) {
    (void)in_sizes; (void)n_in; (void)out_size;
    const float* x  = (const float*)d_in[0];
    const float* W  = (const float*)d_in[1];
    const float* bb = (const float*)d_in[2];
    const float* Wr = (const float*)d_in[3];
    const float* br = (const float*)d_in[4];
    const float* Wz = (const float*)d_in[5];
    const float* bz = (const float*)d_in[6];
    const float* ch[4]; const float* cr[4]; const float* cz[4];
    for (int i = 0; i < 4; i++) {
        ch[i] = (const float*)d_in[7 + 3 * i + 0];
        cr[i] = (const float*)d_in[7 + 3 * i + 1];
        cz[i] = (const float*)d_in[7 + 3 * i + 2];
    }
    float* out = (float*)d_out;

    dim3 grid(1, 256, 12);
    gemm3_kernel<<<grid, 256>>>(x, W, bb, Wr, br, Wz, bz);

    size_t smem_bytes = 57600 * sizeof(float);   // 230,400 B
    cudaFuncSetAttribute(scan_kernel,
                         cudaFuncAttributeMaxDynamicSharedMemorySize,
                         (int)smem_bytes);
    scan_kernel<<<(NBATCH / 2) * 4, 512, smem_bytes>>>(
        ch[0], cr[0], cz[0],
        ch[1], cr[1], cz[1],
        ch[2], cr[2], cz[2],
        ch[3], cr[3], cz[3],
        out);
}

// round 16
// speedup vs baseline: 1.0804x; 1.0804x over previous
#include <cuda_runtime.h>
#include <cstdint>

// ---------------------------------------------------------------------------
// ClockworkGRU  v16 (= v15 with the output stage restored to R13 semantics):
//   * biases staged into SMEM via cp.async -> DRAM latency off the barriered
//     dot critical path.
//   * block 0 redundant per rank (full SMEM matrices); odd steps cluster-free.
//   * streamed r/hn dots 128-deep, z dots 64-deep.
//   * output stage: even steps write ALL blocks at t (+ pre-write t+1 for
//     blocks 1-3); odd steps write block 0 only.
// ---------------------------------------------------------------------------

#define GM 32768
#define GK 512
#define GN 512
#define SEQ_LEN 512
#define NBATCH 64

__device__ float g_proj[3ull * GM * GN];

__constant__ int c_OFF[4]  = {0, 128, 384, 768};
__constant__ int c_SRs[4]  = {0, 2, 3, 4};       // r segs (128-deep)
__constant__ int c_RB[4]   = {0, 0, 256, 832};   // r partial bases in rp
__constant__ int c_SZs[4]  = {0, 4, 6, 8};       // z segs (64-deep)
__constant__ int c_ZB[4]   = {0, 0, 256, 640};   // z partial bases in zp
__constant__ int c_SHs[4]  = {0, 2, 3, 4};       // hn segs (128-deep)
__constant__ int c_HB[4]   = {0, 512, 640, 832}; // hn bases (alias rp)
__constant__ int c_RBB[4]  = {0, 256, 384, 576};     // r bias bases in buf
__constant__ int c_ZBB[4]  = {832, 1088, 1152, 1216};// z bias bases in buf
__constant__ int c_HBB[4]  = {0, 256, 320, 384};     // h bias bases in buf

// ---------------- helpers ----------------------------------------------------
__device__ __forceinline__ unsigned long long pack2(float x, float y) {
    unsigned long long r;
    asm("mov.b64 %0, {%1, %2};" : "=l"(r) : "f"(x), "f"(y));
    return r;
}
__device__ __forceinline__ void fma2(unsigned long long& d,
                                     unsigned long long a,
                                     unsigned long long b) {
    asm("fma.rn.f32x2 %0, %1, %2, %0;" : "+l"(d) : "l"(a), "l"(b));
}
__device__ __forceinline__ float2 unpack2(unsigned long long v) {
    float2 r;
    asm("mov.b64 {%0, %1}, %2;" : "=f"(r.x), "=f"(r.y) : "l"(v));
    return r;
}
__device__ __forceinline__ float sigmoidf_(float x) {
    return 1.0f / (1.0f + __expf(-x));
}
__device__ __forceinline__ uint32_t smem_u32(const void* p) {
    return (uint32_t)__cvta_generic_to_shared(p);
}
__device__ __forceinline__ uint32_t mapa_u32(uint32_t addr, uint32_t rank) {
    uint32_t r;
    asm("mapa.shared::cluster.u32 %0, %1, %2;" : "=r"(r) : "r"(addr), "r"(rank));
    return r;
}
__device__ __forceinline__ void st_cluster_b64(uint32_t a, float x, float y) {
    unsigned long long v = pack2(x, y);
    asm volatile("st.shared::cluster.b64 [%0], %1;" :: "r"(a), "l"(v) : "memory");
}
__device__ __forceinline__ void cp_async4(uint32_t dst, const float* src) {
    asm volatile("cp.async.ca.shared.global [%0], [%1], 4;"
                 :: "r"(dst), "l"(src));
}
#define CP_COMMIT() asm volatile("cp.async.commit_group;" ::: "memory")
#define CP_WAIT0()  asm volatile("cp.async.wait_group 0;"  ::: "memory")
#define CLUSTER_SYNC() do {                                           \
    asm volatile("barrier.cluster.arrive.aligned;" ::: "memory");     \
    asm volatile("barrier.cluster.wait.aligned;"   ::: "memory");     \
} while (0)
#define CLUSTER_ARRIVE() \
    asm volatile("barrier.cluster.arrive.aligned;" ::: "memory")
#define CLUSTER_WAIT() \
    asm volatile("barrier.cluster.wait.aligned;"   ::: "memory")

// ---------------------------------------------------------------------------
// Clockwork-sparse GEMM (unchanged — measured ~0.43 ms)
// ---------------------------------------------------------------------------
#define BM 128
#define BN 128
#define BKK 8

__global__ void __launch_bounds__(256) gemm3_kernel(
    const float* __restrict__ A,
    const float* __restrict__ W0, const float* __restrict__ b0,
    const float* __restrict__ W1, const float* __restrict__ b1,
    const float* __restrict__ W2, const float* __restrict__ b2)
{
    __shared__ float As[BKK][BM];
    __shared__ float Bs[BKK][BN];

    const int zi = blockIdx.z;
    const int z  = zi >> 2;
    const int cb = zi & 3;
    const int rpb_log = 9 - cb;
    const int ntiles = (NBATCH << rpb_log) >> 7;
    if ((int)blockIdx.y >= ntiles) return;

    const float* W    = (z == 0) ? W0 : (z == 1 ? W1 : W2);
    const float* bias = (z == 0) ? b0 : (z == 1 ? b1 : b2);
    float* C = g_proj + (size_t)z * GM * GN;

    const int m0 = blockIdx.y * BM;
    const int n0 = cb * 128;
    const int tid = threadIdx.x;

    const int a_row = tid >> 1;
    const int a_k   = (tid & 1) * 4;
    const int b_row = tid >> 5;
    const int b_col = (tid & 31) * 4;

    const int warp = tid >> 5;
    const int lane = tid & 31;
    const int row0 = (warp & 3) * 32 + (lane & 3) * 8;
    const int col0 = (warp >> 2) * 64 + (lane >> 2) * 8;

    const int rpb_mask = (1 << rpb_log) - 1;
    const int gA = m0 + a_row;
    const int arow_act = ((gA >> rpb_log) << 9) + ((gA & rpb_mask) << cb);

    unsigned long long acc[8][4];
#pragma unroll
    for (int i = 0; i < 8; i++)
#pragma unroll
        for (int j = 0; j < 4; j++) acc[i][j] = 0ull;

    const float* Aptr = A + (size_t)arow_act * GK + a_k;
    const float* Wptr = W + (size_t)b_row * GN + n0 + b_col;

    float4 ra = *(const float4*)Aptr;
    float4 rb = *(const float4*)Wptr;

    const int KT = GK / BKK;
    for (int kt = 0; kt < KT; kt++) {
        As[a_k + 0][a_row] = ra.x;
        As[a_k + 1][a_row] = ra.y;
        As[a_k + 2][a_row] = ra.z;
        As[a_k + 3][a_row] = ra.w;
        *(float4*)&Bs[b_row][b_col] = rb;
        __syncthreads();

        if (kt + 1 < KT) {
            ra = *(const float4*)(Aptr + (kt + 1) * BKK);
            rb = *(const float4*)(Wptr + (size_t)(kt + 1) * BKK * GN);
        }

#pragma unroll
        for (int k = 0; k < BKK; k++) {
            float4 a0 = *(const float4*)&As[k][row0];
            float4 a1 = *(const float4*)&As[k][row0 + 4];
            ulonglong2 bq0 = *(const ulonglong2*)&Bs[k][col0];
            ulonglong2 bq1 = *(const ulonglong2*)&Bs[k][col0 + 4];
            unsigned long long av[8];
            av[0] = pack2(a0.x, a0.x); av[1] = pack2(a0.y, a0.y);
            av[2] = pack2(a0.z, a0.z); av[3] = pack2(a0.w, a0.w);
            av[4] = pack2(a1.x, a1.x); av[5] = pack2(a1.y, a1.y);
            av[6] = pack2(a1.z, a1.z); av[7] = pack2(a1.w, a1.w);
#pragma unroll
            for (int i = 0; i < 8; i++) {
                fma2(acc[i][0], av[i], bq0.x);
                fma2(acc[i][1], av[i], bq0.y);
                fma2(acc[i][2], av[i], bq1.x);
                fma2(acc[i][3], av[i], bq1.y);
            }
        }
        __syncthreads();
    }

    float bb[8];
#pragma unroll
    for (int j = 0; j < 8; j++) bb[j] = bias[n0 + col0 + j];

#pragma unroll
    for (int i = 0; i < 8; i++) {
        float o[8];
#pragma unroll
        for (int jp = 0; jp < 4; jp++) {
            float2 v = unpack2(acc[i][jp]);
            o[2 * jp]     = v.x + bb[2 * jp];
            o[2 * jp + 1] = v.y + bb[2 * jp + 1];
        }
        const int g2 = m0 + row0 + i;
        const int crow = ((g2 >> rpb_log) << 9) + ((g2 & rpb_mask) << cb);
        size_t base = (size_t)crow * GN + n0 + col0;
        *(float4*)&C[base]     = make_float4(o[0], o[1], o[2], o[3]);
        *(float4*)&C[base + 4] = make_float4(o[4], o[5], o[6], o[7]);
    }
}

// ---------------------------------------------------------------------------
// warp-coalesced 2-row dots
// ---------------------------------------------------------------------------

template<int WIDE, int KD>
__device__ __forceinline__ void wdot_wide2(const float* __restrict__ Wp, int stride,
                                           const float* __restrict__ h0,
                                           const float* __restrict__ h1,
                                           float* a0, float* a1, int lane)
{
    const float* p = Wp + lane * 4;
    float4 A[8], B[8];
#pragma unroll
    for (int r = 0; r < 8; r++) A[r] = *(const float4*)(p + (size_t)r * stride);
#pragma unroll
    for (int kb = 0; kb < KD; kb += 16) {
#pragma unroll
        for (int r = 0; r < 8; r++)
            B[r] = *(const float4*)(p + (size_t)(kb + 8 + r) * stride);
#pragma unroll
        for (int r = 0; r < 8; r++) {
            float x0 = h0[kb + r], x1 = h1[kb + r];
            a0[0] = fmaf(x0, A[r].x, a0[0]); a0[1] = fmaf(x0, A[r].y, a0[1]);
            a0[2] = fmaf(x0, A[r].z, a0[2]); a0[3] = fmaf(x0, A[r].w, a0[3]);
            a1[0] = fmaf(x1, A[r].x, a1[0]); a1[1] = fmaf(x1, A[r].y, a1[1]);
            a1[2] = fmaf(x1, A[r].z, a1[2]); a1[3] = fmaf(x1, A[r].w, a1[3]);
        }
        if (kb + 16 < KD) {
#pragma unroll
            for (int r = 0; r < 8; r++)
                A[r] = *(const float4*)(p + (size_t)(kb + 16 + r) * stride);
        }
#pragma unroll
        for (int r = 0; r < 8; r++) {
            float x0 = h0[kb + 8 + r], x1 = h1[kb + 8 + r];
            a0[0] = fmaf(x0, B[r].x, a0[0]); a0[1] = fmaf(x0, B[r].y, a0[1]);
            a0[2] = fmaf(x0, B[r].z, a0[2]); a0[3] = fmaf(x0, B[r].w, a0[3]);
            a1[0] = fmaf(x1, B[r].x, a1[0]); a1[1] = fmaf(x1, B[r].y, a1[1]);
            a1[2] = fmaf(x1, B[r].z, a1[2]); a1[3] = fmaf(x1, B[r].w, a1[3]);
        }
    }
}

__device__ __forceinline__ void w8s2_block(const float* __restrict__ p, int stride,
                                           const float* __restrict__ h0,
                                           const float* __restrict__ h1,
                                           int sr, float* a0, float* a1)
{
    float4 A[8], B[8];
#pragma unroll
    for (int i = 0; i < 8; i++)
        A[i] = *(const float4*)(p + (size_t)(i * 4) * stride);
#pragma unroll
    for (int i = 0; i < 8; i++)
        B[i] = *(const float4*)(p + (size_t)((i + 8) * 4) * stride);
#pragma unroll
    for (int i = 0; i < 8; i++) {
        float x0 = h0[i * 4 + sr], x1 = h1[i * 4 + sr];
        a0[0] = fmaf(x0, A[i].x, a0[0]); a0[1] = fmaf(x0, A[i].y, a0[1]);
        a0[2] = fmaf(x0, A[i].z, a0[2]); a0[3] = fmaf(x0, A[i].w, a0[3]);
        a1[0] = fmaf(x1, A[i].x, a1[0]); a1[1] = fmaf(x1, A[i].y, a1[1]);
        a1[2] = fmaf(x1, A[i].z, a1[2]); a1[3] = fmaf(x1, A[i].w, a1[3]);
    }
#pragma unroll
    for (int i = 0; i < 8; i++) {
        float x0 = h0[(i + 8) * 4 + sr], x1 = h1[(i + 8) * 4 + sr];
        a0[0] = fmaf(x0, B[i].x, a0[0]); a0[1] = fmaf(x0, B[i].y, a0[1]);
        a0[2] = fmaf(x0, B[i].z, a0[2]); a0[3] = fmaf(x0, B[i].w, a0[3]);
        a1[0] = fmaf(x1, B[i].x, a1[0]); a1[1] = fmaf(x1, B[i].y, a1[1]);
        a1[2] = fmaf(x1, B[i].z, a1[2]); a1[3] = fmaf(x1, B[i].w, a1[3]);
    }
}

template<int NSEG>
__device__ __forceinline__ void wdot_w8s2n(const float* __restrict__ Wp, int stride,
                                           const float* __restrict__ h0,
                                           const float* __restrict__ h1,
                                           float* a0, float* a1, int lane)
{
    const int sr = lane >> 3, sc = lane & 7;
    const float* p = Wp + sr * stride + sc * 4;
#pragma unroll
    for (int s = 0; s < NSEG; s++)
        w8s2_block(p + (size_t)(s * 64) * stride, stride,
                   h0 + s * 64, h1 + s * 64, sr, a0, a1);
#pragma unroll
    for (int j = 0; j < 4; j++) {
        a0[j] += __shfl_xor_sync(0xffffffffu, a0[j], 8);
        a0[j] += __shfl_xor_sync(0xffffffffu, a0[j], 16);
        a1[j] += __shfl_xor_sync(0xffffffffu, a1[j], 8);
        a1[j] += __shfl_xor_sync(0xffffffffu, a1[j], 16);
    }
}

__device__ __forceinline__ void dot_b0_64(const float* __restrict__ w,
                                          const float* __restrict__ h0,
                                          const float* __restrict__ h1,
                                          float2& a0, float2& a1)
{
#pragma unroll 16
    for (int k = 0; k < 64; k++) {
        float2 ww = *(const float2*)&w[k << 7];
        float x0 = h0[k], x1 = h1[k];
        a0.x = fmaf(x0, ww.x, a0.x); a0.y = fmaf(x0, ww.y, a0.y);
        a1.x = fmaf(x1, ww.x, a1.x); a1.y = fmaf(x1, ww.y, a1.y);
    }
}

// ---------------------------------------------------------------------------
__global__ void __launch_bounds__(512, 1) __cluster_dims__(4, 1, 1)
scan_kernel(
    const float* __restrict__ ch0, const float* __restrict__ cr0, const float* __restrict__ cz0,
    const float* __restrict__ ch1, const float* __restrict__ cr1, const float* __restrict__ cz1,
    const float* __restrict__ ch2, const float* __restrict__ cr2, const float* __restrict__ cz2,
    const float* __restrict__ ch3, const float* __restrict__ cr3, const float* __restrict__ cz3,
    float* __restrict__ out)
{
    extern __shared__ float smem[];
    float* h_s   = smem;              // 1024
    float* rh_s  = smem + 1024;       // 2560
    float* b0rp  = smem + 3584;       // 512
    float* b0zp  = smem + 4096;       // 512
    float* rp    = smem + 4608;       // 1856 (r partials; hn partials alias)
    float* zp    = smem + 6464;       // 1152
    float* buf   = smem + 7616;       // 1280 bias staging
    float* cr0_s = smem + 8896;       // 16384
    float* cz0_s = smem + 25280;      // 16384
    float* ch0_s = smem + 41664;      // 16384  (end 58048 = 232,192 B)

    const int rank = blockIdx.x & 3;
    const int bp   = blockIdx.x >> 2;
    const int tid  = threadIdx.x;
    const int wid  = tid >> 5;
    const int lane = tid & 31;

    {
        const float4* s1 = (const float4*)cr0; float4* d1 = (float4*)cr0_s;
        const float4* s2 = (const float4*)cz0; float4* d2 = (float4*)cz0_s;
        const float4* s3 = (const float4*)ch0; float4* d3 = (float4*)ch0_s;
        for (int i = tid; i < 4096; i += 512) {
            d1[i] = s1[i]; d2[i] = s2[i]; d3[i] = s3[i];
        }
    }
    h_s[tid] = 0.0f; h_s[512 + tid] = 0.0f;
    __syncthreads();
    CLUSTER_SYNC();

    uint32_t peer_rh[3], peer_h[3];
    {
        int p = 0;
        for (int r = 0; r < 4; r++) {
            if (r == rank) continue;
            peer_rh[p] = mapa_u32(smem_u32(rh_s), (uint32_t)r);
            peer_h[p]  = mapa_u32(smem_u32(h_s),  (uint32_t)r);
            p++;
        }
    }
    const uint32_t buf_sa = smem_u32(buf);

    const float* xt  = g_proj;
    const float* xrt = g_proj + (size_t)GM * GN;
    const float* xzt = g_proj + 2ull * GM * GN;

    for (int t = 0; t < SEQ_LEN; t++) {
        const bool aa1 = (t & 1) == 0, aa2 = (t & 3) == 0, aa3 = (t & 7) == 0;
        int sact[3]; int ns = 0;
        if (aa1) sact[ns++] = 1;
        if (aa2) sact[ns++] = 2;
        if (aa3) sact[ns++] = 3;

        const size_t xr0 = ((size_t)(bp * 2 + 0) * SEQ_LEN + t) * GN;
        const size_t xr1 = ((size_t)(bp * 2 + 1) * SEQ_LEN + t) * GN;

        if (aa1 && t > 0) CLUSTER_WAIT();

        // ============ pass 1 ================================================
        // (0) stage r/z biases via cp.async
        for (int s = tid; s < 1280; s += 512) {
            const float* src = nullptr;
            size_t xr;
            if (s < 256) {
                xr = (s & 128) ? xr1 : xr0;
                src = &xrt[xr + (s & 127)];
            } else if (s < 384) {
                if (aa1) { const int q = s - 256; xr = (q & 64) ? xr1 : xr0;
                           src = &xrt[xr + rank * 64 + (q & 63)]; }
            } else if (s < 576) {
                if (aa2) { const int q = s - 384; xr = (q >= 96) ? xr1 : xr0;
                           src = &xrt[xr + rank * 96 + (q % 96)]; }
            } else if (s < 832) {
                if (aa3) { const int q = s - 576; xr = (q & 128) ? xr1 : xr0;
                           src = &xrt[xr + rank * 128 + (q & 127)]; }
            } else if (s < 1088) {
                const int q = s - 832;
                xr = (q & 128) ? xr1 : xr0;
                src = &xzt[xr + (q & 127)];
            } else if (s < 1152) {
                if (aa1) { const int q = s - 1088; xr = (q & 32) ? xr1 : xr0;
                           src = &xzt[xr + 128 + rank * 32 + (q & 31)]; }
            } else if (s < 1216) {
                if (aa2) { const int q = s - 1152; xr = (q & 32) ? xr1 : xr0;
                           src = &xzt[xr + 256 + rank * 32 + (q & 31)]; }
            } else {
                if (aa3) { const int q = s - 1216; xr = (q & 32) ? xr1 : xr0;
                           src = &xzt[xr + 384 + rank * 32 + (q & 31)]; }
            }
            if (src) cp_async4(buf_sa + (uint32_t)s * 4u, src);
        }
        CP_COMMIT();

        // (a) streamed warp tasks (reverse warp order)
        if (ns > 0) {
            const int nwt = (aa1 ? 8 : 0) + (aa2 ? 9 : 0) + (aa3 ? 12 : 0);
            for (int wt = 15 - wid; wt < nwt; wt += 16) {
                int k = wt;
                float A0[4] = {0,0,0,0}, A1[4] = {0,0,0,0};
                if (aa1) {
                    if (k < 4) {                      // b1 r
                        const int g = k & 1, seg = k >> 1;
                        wdot_w8s2n<2>(cr1 + (size_t)(seg * 128) * 256
                                          + rank * 64 + g * 32, 256,
                                      h_s + seg * 128, h_s + 512 + seg * 128,
                                      A0, A1, lane);
                        if (lane < 8) {
                            const int c = g * 32 + lane * 4;
                            float* P = rp + seg * 128 + c;
                            *(float4*)P        = make_float4(A0[0],A0[1],A0[2],A0[3]);
                            *(float4*)(P + 64) = make_float4(A1[0],A1[1],A1[2],A1[3]);
                        }
                        continue;
                    }
                    k -= 4;
                    if (k < 4) {                      // b1 z
                        const int seg = k;
                        wdot_w8s2n<1>(cz1 + (size_t)(seg * 64) * 128 + rank * 32,
                                      128, h_s + seg * 64, h_s + 512 + seg * 64,
                                      A0, A1, lane);
                        if (lane < 8) {
                            const int c = lane * 4;
                            float* P = zp + seg * 64 + c;
                            *(float4*)P        = make_float4(A0[0],A0[1],A0[2],A0[3]);
                            *(float4*)(P + 32) = make_float4(A1[0],A1[1],A1[2],A1[3]);
                        }
                        continue;
                    }
                    k -= 4;
                }
                if (aa2) {
                    if (k < 3) {                      // b2 r
                        const int seg = k;
                        if (lane < 24) {
                            wdot_wide2<24, 128>(cr2 + (size_t)(seg * 128) * 384
                                                    + rank * 96, 384,
                                                h_s + seg * 128,
                                                h_s + 512 + seg * 128,
                                                A0, A1, lane);
                            const int c = lane * 4;
                            float* P = rp + 256 + seg * 192 + c;
                            *(float4*)P        = make_float4(A0[0],A0[1],A0[2],A0[3]);
                            *(float4*)(P + 96) = make_float4(A1[0],A1[1],A1[2],A1[3]);
                        }
                        continue;
                    }
                    k -= 3;
                    if (k < 6) {                      // b2 z
                        const int seg = k;
                        wdot_w8s2n<1>(cz2 + (size_t)(seg * 64) * 128 + rank * 32,
                                      128, h_s + seg * 64, h_s + 512 + seg * 64,
                                      A0, A1, lane);
                        if (lane < 8) {
                            const int c = lane * 4;
                            float* P = zp + 256 + seg * 64 + c;
                            *(float4*)P        = make_float4(A0[0],A0[1],A0[2],A0[3]);
                            *(float4*)(P + 32) = make_float4(A1[0],A1[1],A1[2],A1[3]);
                        }
                        continue;
                    }
                    k -= 6;
                }
                if (k < 4) {                          // b3 r
                    const int seg = k;
                    wdot_wide2<32, 128>(cr3 + (size_t)(seg * 128) * 512
                                            + rank * 128, 512,
                                        h_s + seg * 128, h_s + 512 + seg * 128,
                                        A0, A1, lane);
                    const int c = lane * 4;
                    float* P = rp + 832 + seg * 256 + c;
                    *(float4*)P         = make_float4(A0[0],A0[1],A0[2],A0[3]);
                    *(float4*)(P + 128) = make_float4(A1[0],A1[1],A1[2],A1[3]);
                } else {                              // b3 z
                    const int seg = k - 4;
                    wdot_w8s2n<1>(cz3 + (size_t)(seg * 64) * 128 + rank * 32,
                                  128, h_s + seg * 64, h_s + 512 + seg * 64,
                                  A0, A1, lane);
                    if (lane < 8) {
                        const int c = lane * 4;
                        float* P = zp + 640 + seg * 64 + c;
                        *(float4*)P        = make_float4(A0[0],A0[1],A0[2],A0[3]);
                        *(float4*)(P + 32) = make_float4(A1[0],A1[1],A1[2],A1[3]);
                    }
                }
            }
        }
        // (b) block0 r/z tasks on warps 0-7 (redundant, SMEM)
        if (tid < 256) {
            const bool isZ = tid >= 128;
            const int r2 = tid & 127;
            const int seg = r2 >> 6, c = (r2 & 63) * 2;
            float2 A0 = {0.f, 0.f}, A1 = {0.f, 0.f};
            const float* w = (isZ ? cz0_s : cr0_s) + (seg * 64) * 128 + c;
            dot_b0_64(w, h_s + seg * 64, h_s + 512 + seg * 64, A0, A1);
            float* P = (isZ ? b0zp : b0rp) + seg * 256 + c;
            *(float2*)P         = A0;
            *(float2*)(P + 128) = A1;
        }
        CP_WAIT0();
        __syncthreads();

        // ============ pass 2: reduce r (+bias) → rh =========================
        {
            int pcount[3]; int nst = 0;
            for (int a = 0; a < ns; a++) {
                pcount[a] = (sact[a] + 1) * 16;
                nst += pcount[a];
            }
            const int total2 = 128 + 2 * nst;
            for (int s = tid; s < total2; s += 512) {
                if (s < 128) {
                    const int row = s & 1;
                    const int c = (s >> 1) * 2;
                    const float* P = b0rp + row * 128 + c;
                    const float* B = buf + row * 128 + c;
                    const float s0 = P[0] + P[256] + B[0];
                    const float s1 = P[1] + P[257] + B[1];
                    const float* hh = h_s + row * 512;
                    rh_s[row * 1280 + c]     = sigmoidf_(s0) * hh[c];
                    rh_s[row * 1280 + c + 1] = sigmoidf_(s1) * hh[c + 1];
                } else {
                    const int s2 = s - 128;
                    const int row = s2 & 1;
                    int p = s2 >> 1;
                    int i = 1;
                    for (int a = 0; a < ns; a++) {
                        if (p < pcount[a]) { i = sact[a]; break; }
                        p -= pcount[a];
                    }
                    const int colsP = (i + 1) * 32;
                    const int c2 = p * 2;
                    const int j = rank * colsP + c2;
                    const float* P = rp + c_RB[i] + row * colsP + c2;
                    const float* B = buf + c_RBB[i] + row * colsP + c2;
                    float s0 = B[0], s1 = B[1];
                    const int nsg = c_SRs[i];
                    for (int sg = 0; sg < nsg; sg++) {
                        s0 += P[sg * 2 * colsP];
                        s1 += P[sg * 2 * colsP + 1];
                    }
                    const float* hh = h_s + row * 512;
                    const float v0 = sigmoidf_(s0) * hh[j];
                    const float v1 = sigmoidf_(s1) * hh[j + 1];
                    const int idx = c_OFF[i] + j;
                    rh_s[row * 1280 + idx]     = v0;
                    rh_s[row * 1280 + idx + 1] = v1;
                    const uint32_t off = (uint32_t)(row * 1280 + idx) * 4u;
                    st_cluster_b64(peer_rh[0] + off, v0, v1);
                    st_cluster_b64(peer_rh[1] + off, v0, v1);
                    st_cluster_b64(peer_rh[2] + off, v0, v1);
                }
            }
        }
        if (ns > 0) CLUSTER_SYNC();
        else        __syncthreads();

        // ============ pass 3: hn dots (+ stage h biases) ====================
        for (int s = tid; s < 448; s += 512) {
            const float* src = nullptr;
            size_t xr;
            if (s < 256) {
                xr = (s & 128) ? xr1 : xr0;
                src = &xt[xr + (s & 127)];
            } else if (s < 320) {
                if (aa1) { const int q = s - 256; xr = (q & 32) ? xr1 : xr0;
                           src = &xt[xr + 128 + rank * 32 + (q & 31)]; }
            } else if (s < 384) {
                if (aa2) { const int q = s - 320; xr = (q & 32) ? xr1 : xr0;
                           src = &xt[xr + 256 + rank * 32 + (q & 31)]; }
            } else {
                if (aa3) { const int q = s - 384; xr = (q & 32) ? xr1 : xr0;
                           src = &xt[xr + 384 + rank * 32 + (q & 31)]; }
            }
            if (src) cp_async4(buf_sa + (uint32_t)s * 4u, src);
        }
        CP_COMMIT();

        if (ns > 0) {
            const int nwh = (aa1 ? 2 : 0) + (aa2 ? 3 : 0) + (aa3 ? 4 : 0);
            for (int wt = 15 - wid; wt < nwh; wt += 16) {
                int k = wt;
                float A0[4] = {0,0,0,0}, A1[4] = {0,0,0,0};
                int i, seg;
                const float* base;
                if (aa1 && k < 2)      { i = 1; seg = k; base = ch1; }
                else {
                    if (aa1) k -= 2;
                    if (aa2 && k < 3)  { i = 2; seg = k; base = ch2; }
                    else { if (aa2) k -= 3; i = 3; seg = k; base = ch3; }
                }
                wdot_w8s2n<2>(base + (size_t)(seg * 128) * 128 + rank * 32, 128,
                              rh_s + c_OFF[i] + seg * 128,
                              rh_s + 1280 + c_OFF[i] + seg * 128, A0, A1, lane);
                if (lane < 8) {
                    const int c = lane * 4;
                    float* P = rp + c_HB[i] + seg * 64 + c;
                    *(float4*)P        = make_float4(A0[0],A0[1],A0[2],A0[3]);
                    *(float4*)(P + 32) = make_float4(A1[0],A1[1],A1[2],A1[3]);
                }
            }
        }
        if (tid < 128) {
            const int seg = tid >> 6, c = (tid & 63) * 2;
            float2 A0 = {0.f, 0.f}, A1 = {0.f, 0.f};
            dot_b0_64(ch0_s + (seg * 64) * 128 + c,
                      rh_s + seg * 64, rh_s + 1280 + seg * 64, A0, A1);
            float* P = rp + seg * 256 + c;   // b0h aliases rp[0:512)
            *(float2*)P         = A0;
            *(float2*)(P + 128) = A1;
        }
        CP_WAIT0();
        __syncthreads();

        // ============ pass 4: reduce z/hn (+bias), gate, update h ==========
        {
            const int total4 = 128 + 2 * (ns * 16);
            for (int s = tid; s < total4; s += 512) {
                if (s < 128) {
                    const int row = s & 1;
                    const int c = (s >> 1) * 2;
                    const float* Pz = b0zp + row * 128 + c;
                    const float* Ph = rp + row * 128 + c;
                    const float z0 = Pz[0] + Pz[256] + buf[832 + row * 128 + c];
                    const float z1 = Pz[1] + Pz[257] + buf[832 + row * 128 + c + 1];
                    const float n0 = Ph[0] + Ph[256] + buf[row * 128 + c];
                    const float n1 = Ph[1] + Ph[257] + buf[row * 128 + c + 1];
                    const float zz0 = sigmoidf_(z0), zz1 = sigmoidf_(z1);
                    const float hn0 = sigmoidf_(n0), hn1 = sigmoidf_(n1);
                    float* hh = h_s + row * 512;
                    hh[c]     = zz0 * hn0 + (1.0f - zz0) * hh[c];
                    hh[c + 1] = zz1 * hn1 + (1.0f - zz1) * hh[c + 1];
                } else {
                    const int s2 = s - 128;
                    const int row = s2 & 1;
                    const int p = s2 >> 1;
                    const int i = sact[p >> 4];
                    const int c2 = (p & 15) * 2;
                    const int lc = rank * 32 + c2;
                    const int gc = (i << 7) + lc;
                    const float* Pz = zp + c_ZB[i] + row * 32 + c2;
                    const float* Ph = rp + c_HB[i] + row * 32 + c2;
                    float z0 = buf[c_ZBB[i] + row * 32 + c2];
                    float z1 = buf[c_ZBB[i] + row * 32 + c2 + 1];
                    float n0 = buf[c_HBB[i] + row * 32 + c2];
                    float n1 = buf[c_HBB[i] + row * 32 + c2 + 1];
                    const int nz = c_SZs[i];
                    for (int sg = 0; sg < nz; sg++) {
                        z0 += Pz[sg * 64]; z1 += Pz[sg * 64 + 1];
                    }
                    const int nh = c_SHs[i];
                    for (int sg = 0; sg < nh; sg++) {
                        n0 += Ph[sg * 64]; n1 += Ph[sg * 64 + 1];
                    }
                    const float zz0 = sigmoidf_(z0), zz1 = sigmoidf_(z1);
                    const float hn0 = sigmoidf_(n0), hn1 = sigmoidf_(n1);
                    float* hh = h_s + row * 512;
                    const float v0 = zz0 * hn0 + (1.0f - zz0) * hh[gc];
                    const float v1 = zz1 * hn1 + (1.0f - zz1) * hh[gc + 1];
                    hh[gc] = v0; hh[gc + 1] = v1;
                    const uint32_t off = (uint32_t)(row * 512 + gc) * 4u;
                    st_cluster_b64(peer_h[0] + off, v0, v1);
                    st_cluster_b64(peer_h[1] + off, v0, v1);
                    st_cluster_b64(peer_h[2] + off, v0, v1);
                }
            }
        }
        __syncthreads();

        // ============ output (ALL blocks every step — R13 semantics) ========
        if (ns > 0) {
            if (tid < 256) {
                // row t: own 32-col slice of all 4 blocks, both batch rows
                const int row = tid >> 7;
                const int idx = tid & 127;
                const int i = idx >> 5, c = idx & 31;
                const int gc = i * 128 + rank * 32 + c;
                const size_t xr = row ? xr1 : xr0;
                out[xr + gc] = h_s[row * 512 + gc];
            } else if (tid < 448) {
                // pre-write row t+1 for blocks 1-3 (unchanged at odd t+1)
                const int s = tid - 256;
                const int row = s / 96;
                const int idx = s % 96;
                const int i = 1 + (idx >> 5), c = idx & 31;
                const int gc = i * 128 + rank * 32 + c;
                const size_t xr = (row ? xr1 : xr0) + GN;
                out[xr + gc] = h_s[row * 512 + gc];
            }
            CLUSTER_ARRIVE();   // completed by WAIT at next even step
        } else {
            // odd step: only block-0 cols changed
            if (tid < 64) {
                const int row = tid >> 5, c = tid & 31;
                const int gc = rank * 32 + c;
                const size_t xr = row ? xr1 : xr0;
                out[xr + gc] = h_s[row * 512 + gc];
            }
        }
    }
    CLUSTER_WAIT();   // balance the final even-step arrive
}

// ---------------------------------------------------------------------------
extern "C" void kernel_launch(void* const* d_in, const int* in_sizes, int n_in,
                              void* d_out, int out_size) {
    (void)in_sizes; (void)n_in; (void)out_size;
    const float* x  = (const float*)d_in[0];
    const float* W  = (const float*)d_in[1];
    const float* bb = (const float*)d_in[2];
    const float* Wr = (const float*)d_in[3];
    const float* br = (const float*)d_in[4];
    const float* Wz = (const float*)d_in[5];
    const float* bz = (const float*)d_in[6];
    const float* ch[4]; const float* cr[4]; const float* cz[4];
    for (int i = 0; i < 4; i++) {
        ch[i] = (const float*)d_in[7 + 3 * i + 0];
        cr[i] = (const float*)d_in[7 + 3 * i + 1];
        cz[i] = (const float*)d_in[7 + 3 * i + 2];
    }
    float* out = (float*)d_out;

    dim3 grid(1, 256, 12);
    gemm3_kernel<<<grid, 256>>>(x, W, bb, Wr, br, Wz, bz);

    size_t smem_bytes = 58048 * sizeof(float);   // 232,192 B
    cudaFuncSetAttribute(scan_kernel,
                         cudaFuncAttributeMaxDynamicSharedMemorySize,
                         (int)smem_bytes);
    scan_kernel<<<(NBATCH / 2) * 4, 512, smem_bytes>>>(
        ch[0], cr[0], cz[0],
        ch[1], cr[1], cz[1],
        ch[2], cr[2], cz[2],
        ch[3], cr[3], cz[3],
        out);
}